// round 1
// baseline (speedup 1.0000x reference)
#include <cuda_runtime.h>

#define S_LEN 2048
#define TPB   256
#define CHUNK 8            // S_LEN / TPB
#define RPB   4            // rows per block (amortize weight staging)
#define NWARP (TPB / 32)

// out[row, t] = v2[t]*x[row, t] + bias[t] + acc_t
// acc_{t+1} = d * (acc_t + v[t]*x[row, t]),  acc_0 = 0
// d = clip(decay_value[1], 0.9, 1.0)
__global__ __launch_bounds__(TPB) void decay_scan_kernel(
    const float* __restrict__ x,
    const float* __restrict__ w,      // weight  (S,)
    const float* __restrict__ w2,     // diag_weight (S,)
    const float* __restrict__ bias,   // (S,)
    const float* __restrict__ dv,     // decay_value (2,)
    float* __restrict__ out,
    int nrows)
{
    __shared__ float sv [S_LEN];
    __shared__ float sv2[S_LEN];
    __shared__ float sb [S_LEN];
    __shared__ float warpsum[NWARP];

    const int tid = threadIdx.x;

    // Stage the three shared-by-all-rows vectors into SMEM (vectorized).
    {
        const float4* w4  = (const float4*)w;
        const float4* w24 = (const float4*)w2;
        const float4* b4  = (const float4*)bias;
        float4* sv4  = (float4*)sv;
        float4* sv24 = (float4*)sv2;
        float4* sb4  = (float4*)sb;
        #pragma unroll
        for (int i = tid; i < S_LEN / 4; i += TPB) {
            sv4[i]  = w4[i];
            sv24[i] = w24[i];
            sb4[i]  = b4[i];
        }
    }

    const float d  = fminf(fmaxf(dv[1], 0.9f), 1.0f);
    const float d2 = d * d;
    const float d4 = d2 * d2;
    const float d8 = d4 * d4;

    const int lane = tid & 31;
    const int wid  = tid >> 5;

    // d8^lane, used to apply the warp-carry across lanes. Exact 1.0 when d==1.
    const float d8_lane = exp2f((float)lane * __log2f(d8));

    __syncthreads();

    #pragma unroll 1
    for (int r = 0; r < RPB; ++r) {
        const int  row    = blockIdx.x * RPB + r;
        const bool active = (row < nrows);

        const float* xr   = x   + (size_t)row * S_LEN;
        float*       outr = out + (size_t)row * S_LEN;

        float4 xa = make_float4(0.f, 0.f, 0.f, 0.f);
        float4 xb = xa;
        if (active) {
            xa = ((const float4*)xr)[tid * 2 + 0];
            xb = ((const float4*)xr)[tid * 2 + 1];
        }
        const float4 va = ((const float4*)sv)[tid * 2 + 0];
        const float4 vb = ((const float4*)sv)[tid * 2 + 1];

        float xv[CHUNK] = {xa.x, xa.y, xa.z, xa.w, xb.x, xb.y, xb.z, xb.w};
        float vv[CHUNK] = {va.x, va.y, va.z, va.w, vb.x, vb.y, vb.z, vb.w};

        // Thread-local partial: P = sum_i xv[i]*vv[i]*d^(CHUNK-i)
        float P = 0.f;
        #pragma unroll
        for (int i = 0; i < CHUNK; ++i)
            P = d * (P + xv[i] * vv[i]);

        // Warp-level inclusive scan with constant ratio d8 (Hillis-Steele).
        float inc  = P;
        float mult = d8;
        #pragma unroll
        for (int o = 1; o < 32; o <<= 1) {
            float t = __shfl_up_sync(0xffffffffu, inc, o);
            if (lane >= o) inc = fmaf(mult, t, inc);
            mult *= mult;
        }
        const float d256 = mult;  // d8^32 = d^256

        if (lane == 31) warpsum[wid] = inc;
        __syncthreads();
        if (tid == 0) {
            // Exclusive carry scan over the 8 warp partials.
            float a = 0.f;
            #pragma unroll
            for (int wn = 0; wn < NWARP; ++wn) {
                float t = warpsum[wn];
                warpsum[wn] = a;
                a = fmaf(d256, a, t);
            }
        }
        __syncthreads();

        float laneExc = __shfl_up_sync(0xffffffffu, inc, 1);
        if (lane == 0) laneExc = 0.f;

        // acc at the start of this thread's chunk.
        float acc = fmaf(warpsum[wid], d8_lane, laneExc);

        const float4 v2a = ((const float4*)sv2)[tid * 2 + 0];
        const float4 v2b = ((const float4*)sv2)[tid * 2 + 1];
        const float4 ba  = ((const float4*)sb)[tid * 2 + 0];
        const float4 bb  = ((const float4*)sb)[tid * 2 + 1];
        float v2v[CHUNK] = {v2a.x, v2a.y, v2a.z, v2a.w, v2b.x, v2b.y, v2b.z, v2b.w};
        float bv [CHUNK] = {ba.x,  ba.y,  ba.z,  ba.w,  bb.x,  bb.y,  bb.z,  bb.w};

        float o8[CHUNK];
        #pragma unroll
        for (int i = 0; i < CHUNK; ++i) {
            o8[i] = fmaf(v2v[i], xv[i], acc + bv[i]);
            acc   = d * (acc + xv[i] * vv[i]);
        }

        if (active) {
            ((float4*)outr)[tid * 2 + 0] = make_float4(o8[0], o8[1], o8[2], o8[3]);
            ((float4*)outr)[tid * 2 + 1] = make_float4(o8[4], o8[5], o8[6], o8[7]);
        }
        __syncthreads();  // protect warpsum reuse across row iterations
    }
}

extern "C" void kernel_launch(void* const* d_in, const int* in_sizes, int n_in,
                              void* d_out, int out_size)
{
    const float* x    = (const float*)d_in[0];
    const float* w    = (const float*)d_in[1];
    const float* w2   = (const float*)d_in[2];
    const float* bias = (const float*)d_in[3];
    const float* dv   = (const float*)d_in[4];
    float* out = (float*)d_out;

    const int nrows = in_sizes[0] / S_LEN;           // B*E
    const int grid  = (nrows + RPB - 1) / RPB;

    decay_scan_kernel<<<grid, TPB>>>(x, w, w2, bias, dv, out, nrows);
}

// round 2
// speedup vs baseline: 1.0243x; 1.0243x over previous
#include <cuda_runtime.h>

#define S_LEN 2048
#define TPB   256
#define CHUNK 8            // S_LEN / TPB
#define RPB   8            // rows per block (amortize vector-register staging)
#define NWARP (TPB / 32)

// out[row, t] = v2[t]*x[row, t] + bias[t] + acc_t
// acc_{t+1} = d * (acc_t + v[t]*x[row, t]),  acc_0 = 0
// d = clip(decay_value[1], 0.9, 1.0)
__global__ __launch_bounds__(TPB, 4) void decay_scan_kernel(
    const float* __restrict__ x,
    const float* __restrict__ w,      // weight  (S,)
    const float* __restrict__ w2,     // diag_weight (S,)
    const float* __restrict__ bias,   // (S,)
    const float* __restrict__ dv,     // decay_value (2,)
    float* __restrict__ out,
    int nrows)
{
    __shared__ float warpsum[2][NWARP];   // double-buffered per row parity

    const int tid  = threadIdx.x;
    const int lane = tid & 31;
    const int wid  = tid >> 5;

    // ── Stage the three shared vectors into REGISTERS once per block ──
    // Each thread owns the same 8 sequence positions for every row.
    float vv[CHUNK], v2v[CHUNK], bv[CHUNK];
    {
        const float4 va  = ((const float4*)w )[tid * 2 + 0];
        const float4 vb  = ((const float4*)w )[tid * 2 + 1];
        const float4 v2a = ((const float4*)w2)[tid * 2 + 0];
        const float4 v2b = ((const float4*)w2)[tid * 2 + 1];
        const float4 ba  = ((const float4*)bias)[tid * 2 + 0];
        const float4 bb  = ((const float4*)bias)[tid * 2 + 1];
        vv[0]=va.x;  vv[1]=va.y;  vv[2]=va.z;  vv[3]=va.w;
        vv[4]=vb.x;  vv[5]=vb.y;  vv[6]=vb.z;  vv[7]=vb.w;
        v2v[0]=v2a.x; v2v[1]=v2a.y; v2v[2]=v2a.z; v2v[3]=v2a.w;
        v2v[4]=v2b.x; v2v[5]=v2b.y; v2v[6]=v2b.z; v2v[7]=v2b.w;
        bv[0]=ba.x;  bv[1]=ba.y;  bv[2]=ba.z;  bv[3]=ba.w;
        bv[4]=bb.x;  bv[5]=bb.y;  bv[6]=bb.z;  bv[7]=bb.w;
    }

    const float d  = fminf(fmaxf(dv[1], 0.9f), 1.0f);
    const float d2 = d * d;
    const float d4 = d2 * d2;
    const float d8 = d4 * d4;
    // d8^lane — exact 1.0 when d==1 (log2f(1)=0)
    const float d8_lane = exp2f((float)lane * __log2f(d8));

    #pragma unroll 1
    for (int r = 0; r < RPB; ++r) {
        const int  row    = blockIdx.x * RPB + r;
        const bool active = (row < nrows);

        const float* xr   = x   + (size_t)row * S_LEN;
        float*       outr = out + (size_t)row * S_LEN;

        // Streaming loads — x is never reused, keep it out of L2's way.
        float4 xa = make_float4(0.f, 0.f, 0.f, 0.f);
        float4 xb = xa;
        if (active) {
            xa = __ldcs((const float4*)xr + tid * 2 + 0);
            xb = __ldcs((const float4*)xr + tid * 2 + 1);
        }
        float xv[CHUNK] = {xa.x, xa.y, xa.z, xa.w, xb.x, xb.y, xb.z, xb.w};

        // Thread-local partial: P = sum_i xv[i]*vv[i]*d^(CHUNK-i)
        float P = 0.f;
        #pragma unroll
        for (int i = 0; i < CHUNK; ++i)
            P = d * (P + xv[i] * vv[i]);

        // Warp-level inclusive scan with constant ratio d8 (Hillis-Steele).
        float inc  = P;
        float mult = d8;
        #pragma unroll
        for (int o = 1; o < 32; o <<= 1) {
            float t = __shfl_up_sync(0xffffffffu, inc, o);
            if (lane >= o) inc = fmaf(mult, t, inc);
            mult *= mult;
        }
        const float d256 = mult;  // d8^32 = d^256

        if (lane == 31) warpsum[r & 1][wid] = inc;
        __syncthreads();          // the ONLY barrier per row

        // Every thread computes its own exclusive warp carry from the 8
        // broadcast values (uniform addr per warp → conflict-free LDS).
        float excw = 0.f;
        #pragma unroll
        for (int wn = 0; wn < NWARP - 1; ++wn) {
            if (wn < wid) excw = fmaf(d256, excw, warpsum[r & 1][wn]);
        }

        float laneExc = __shfl_up_sync(0xffffffffu, inc, 1);
        if (lane == 0) laneExc = 0.f;

        // acc at the start of this thread's chunk.
        float acc = fmaf(excw, d8_lane, laneExc);

        float o8[CHUNK];
        #pragma unroll
        for (int i = 0; i < CHUNK; ++i) {
            o8[i] = fmaf(v2v[i], xv[i], acc + bv[i]);
            acc   = d * (acc + xv[i] * vv[i]);
        }

        if (active) {
            __stcs((float4*)outr + tid * 2 + 0,
                   make_float4(o8[0], o8[1], o8[2], o8[3]));
            __stcs((float4*)outr + tid * 2 + 1,
                   make_float4(o8[4], o8[5], o8[6], o8[7]));
        }
        // No trailing barrier: warpsum is double-buffered by row parity, and
        // the next row's write (to buf[(r+1)&1]) is ordered after this row's
        // reads by the barrier inside iteration r+1.
    }
}

extern "C" void kernel_launch(void* const* d_in, const int* in_sizes, int n_in,
                              void* d_out, int out_size)
{
    const float* x    = (const float*)d_in[0];
    const float* w    = (const float*)d_in[1];
    const float* w2   = (const float*)d_in[2];
    const float* bias = (const float*)d_in[3];
    const float* dv   = (const float*)d_in[4];
    float* out = (float*)d_out;

    const int nrows = in_sizes[0] / S_LEN;           // B*E
    const int grid  = (nrows + RPB - 1) / RPB;

    decay_scan_kernel<<<grid, TPB>>>(x, w, w2, bias, dv, out, nrows);
}

// round 3
// speedup vs baseline: 1.3605x; 1.3282x over previous
#include <cuda_runtime.h>
#include <cstdint>

#define S_LEN  2048
#define TPB    256
#define CHUNK  8            // S_LEN / TPB
#define RPB    8            // rows per block
#define NWARP  (TPB / 32)
#define STAGES 4            // cp.async ring depth (3 rows in flight)

__device__ __forceinline__ void cp_async16(uint32_t saddr, const float* gptr) {
    asm volatile("cp.async.cg.shared.global [%0], [%1], 16;\n"
                 :: "r"(saddr), "l"(gptr));
}
__device__ __forceinline__ void cp_commit() {
    asm volatile("cp.async.commit_group;\n" ::);
}
__device__ __forceinline__ void cp_wait3() {
    asm volatile("cp.async.wait_group 3;\n" ::: "memory");
}

// out[row, t] = v2[t]*x[row, t] + bias[t] + acc_t
// acc_{t+1} = d * (acc_t + v[t]*x[row, t]),  acc_0 = 0
// d = clip(decay_value[1], 0.9, 1.0)
__global__ __launch_bounds__(TPB, 4) void decay_scan_kernel(
    const float* __restrict__ x,
    const float* __restrict__ w,      // weight  (S,)
    const float* __restrict__ w2,     // diag_weight (S,)
    const float* __restrict__ bias,   // (S,)
    const float* __restrict__ dv,     // decay_value (2,)
    float* __restrict__ out,
    int nrows)
{
    __shared__ float sx[STAGES][S_LEN];   // 32 KB x ring
    __shared__ float warpsum[2][NWARP];   // double-buffered per row parity

    const int tid  = threadIdx.x;
    const int lane = tid & 31;
    const int wid  = tid >> 5;

    // ── Stage the three shared vectors into REGISTERS once per block ──
    float vv[CHUNK], v2v[CHUNK], bv[CHUNK];
    {
        const float4 va  = ((const float4*)w )[tid * 2 + 0];
        const float4 vb  = ((const float4*)w )[tid * 2 + 1];
        const float4 v2a = ((const float4*)w2)[tid * 2 + 0];
        const float4 v2b = ((const float4*)w2)[tid * 2 + 1];
        const float4 ba  = ((const float4*)bias)[tid * 2 + 0];
        const float4 bb  = ((const float4*)bias)[tid * 2 + 1];
        vv[0]=va.x;  vv[1]=va.y;  vv[2]=va.z;  vv[3]=va.w;
        vv[4]=vb.x;  vv[5]=vb.y;  vv[6]=vb.z;  vv[7]=vb.w;
        v2v[0]=v2a.x; v2v[1]=v2a.y; v2v[2]=v2a.z; v2v[3]=v2a.w;
        v2v[4]=v2b.x; v2v[5]=v2b.y; v2v[6]=v2b.z; v2v[7]=v2b.w;
        bv[0]=ba.x;  bv[1]=ba.y;  bv[2]=ba.z;  bv[3]=ba.w;
        bv[4]=bb.x;  bv[5]=bb.y;  bv[6]=bb.z;  bv[7]=bb.w;
    }

    const float d  = fminf(fmaxf(dv[1], 0.9f), 1.0f);
    const float d2 = d * d;
    const float d4 = d2 * d2;
    const float d8 = d4 * d4;
    // d8^lane — exact 1.0 when d==1 (log2f(1)=0)
    const float d8_lane = exp2f((float)lane * __log2f(d8));

    const int    row0  = blockIdx.x * RPB;
    // Each thread owns the same 32 bytes (8 floats) of every row.
    const float* gbase = x + (size_t)row0 * S_LEN + tid * CHUNK;

    const uint32_t s0     = (uint32_t)__cvta_generic_to_shared(&sx[0][0]);
    const uint32_t my_off = (uint32_t)tid * 32u;   // byte offset inside a stage

    // ── Prologue: put rows 0..STAGES-2 in flight ──
    #pragma unroll
    for (int p = 0; p < STAGES - 1; ++p) {
        if (row0 + p < nrows) {
            const float*   g  = gbase + (size_t)p * S_LEN;
            const uint32_t sa = s0 + (uint32_t)p * (S_LEN * 4) + my_off;
            cp_async16(sa,      g);
            cp_async16(sa + 16, g + 4);
        }
        cp_commit();
    }

    #pragma unroll 1
    for (int r = 0; r < RPB; ++r) {
        // Keep the ring full: issue row r+STAGES-1.
        {
            const int pr = r + STAGES - 1;
            if (pr < RPB && row0 + pr < nrows) {
                const float*   g  = gbase + (size_t)pr * S_LEN;
                const int      st = pr & (STAGES - 1);
                const uint32_t sa = s0 + (uint32_t)st * (S_LEN * 4) + my_off;
                cp_async16(sa,      g);
                cp_async16(sa + 16, g + 4);
            }
            cp_commit();    // always commit (possibly-empty group) → fixed wait count
        }
        // After r+STAGES commits total, ≤3 pending ⇒ row r's group is done.
        cp_wait3();

        const int  row    = row0 + r;
        const bool active = (row < nrows);
        const int  st     = r & (STAGES - 1);

        // Each thread reads back exactly the bytes its own cp.async wrote —
        // wait_group alone orders this, no __syncthreads needed.
        const float4 xa = ((const float4*)sx[st])[tid * 2 + 0];
        const float4 xb = ((const float4*)sx[st])[tid * 2 + 1];
        float xv[CHUNK] = {xa.x, xa.y, xa.z, xa.w, xb.x, xb.y, xb.z, xb.w};

        // Thread-local partial: P = sum_i xv[i]*vv[i]*d^(CHUNK-i)
        float P = 0.f;
        #pragma unroll
        for (int i = 0; i < CHUNK; ++i)
            P = d * (P + xv[i] * vv[i]);

        // Warp-level inclusive scan with constant ratio d8 (Hillis-Steele).
        float inc  = P;
        float mult = d8;
        #pragma unroll
        for (int o = 1; o < 32; o <<= 1) {
            float t = __shfl_up_sync(0xffffffffu, inc, o);
            if (lane >= o) inc = fmaf(mult, t, inc);
            mult *= mult;
        }
        const float d256 = mult;  // d8^32 = d^256

        if (lane == 31) warpsum[r & 1][wid] = inc;
        __syncthreads();          // the ONLY barrier per row

        // Per-thread exclusive warp carry from the 8 broadcast partials
        // (uniform address within each warp → broadcast LDS, conflict-free).
        float excw = 0.f;
        #pragma unroll
        for (int wn = 0; wn < NWARP - 1; ++wn) {
            if (wn < wid) excw = fmaf(d256, excw, warpsum[r & 1][wn]);
        }

        float laneExc = __shfl_up_sync(0xffffffffu, inc, 1);
        if (lane == 0) laneExc = 0.f;

        // acc at the start of this thread's chunk.
        float acc = fmaf(excw, d8_lane, laneExc);

        float* outr = out + (size_t)row * S_LEN + tid * CHUNK;

        // First half: compute 4, store immediately (limits live registers).
        {
            float o0 = fmaf(v2v[0], xv[0], acc + bv[0]);
            acc = d * (acc + xv[0] * vv[0]);
            float o1 = fmaf(v2v[1], xv[1], acc + bv[1]);
            acc = d * (acc + xv[1] * vv[1]);
            float o2 = fmaf(v2v[2], xv[2], acc + bv[2]);
            acc = d * (acc + xv[2] * vv[2]);
            float o3 = fmaf(v2v[3], xv[3], acc + bv[3]);
            acc = d * (acc + xv[3] * vv[3]);
            if (active) __stcs((float4*)outr, make_float4(o0, o1, o2, o3));
        }
        // Second half.
        {
            float o4 = fmaf(v2v[4], xv[4], acc + bv[4]);
            acc = d * (acc + xv[4] * vv[4]);
            float o5 = fmaf(v2v[5], xv[5], acc + bv[5]);
            acc = d * (acc + xv[5] * vv[5]);
            float o6 = fmaf(v2v[6], xv[6], acc + bv[6]);
            acc = d * (acc + xv[6] * vv[6]);
            float o7 = fmaf(v2v[7], xv[7], acc + bv[7]);
            if (active) __stcs((float4*)(outr + 4), make_float4(o4, o5, o6, o7));
        }
        // warpsum is double-buffered by row parity; next row's write (to the
        // other buffer) is ordered after this row's reads by its own barrier.
    }
}

extern "C" void kernel_launch(void* const* d_in, const int* in_sizes, int n_in,
                              void* d_out, int out_size)
{
    const float* x    = (const float*)d_in[0];
    const float* w    = (const float*)d_in[1];
    const float* w2   = (const float*)d_in[2];
    const float* bias = (const float*)d_in[3];
    const float* dv   = (const float*)d_in[4];
    float* out = (float*)d_out;

    const int nrows = in_sizes[0] / S_LEN;           // B*E
    const int grid  = (nrows + RPB - 1) / RPB;

    decay_scan_kernel<<<grid, TPB>>>(x, w, w2, bias, dv, out, nrows);
}